// round 2
// baseline (speedup 1.0000x reference)
#include <cuda_runtime.h>
#include <cuda_bf16.h>
#include <math.h>

// ---------------------------------------------------------------------------
// Problem constants
// ---------------------------------------------------------------------------
#define BATCH     2048
#define SDIM      64
#define ADIM      16
#define HID       256
#define TDIM      32
#define TSTEPS    100
#define CAT       112            // ADIM + TDIM + SDIM
#define ROWS      16             // rows per CTA
#define NCTA      (BATCH / ROWS) // 128

// ---------------------------------------------------------------------------
// Device-global scratch (no allocations allowed)
// ---------------------------------------------------------------------------
__device__ float g_x[BATCH * ADIM];
__device__ float g_temb[TSTEPS * TDIM];
__device__ float g_srac[TSTEPS];
__device__ float g_sracm1[TSTEPS];
__device__ float g_c1[TSTEPS];
__device__ float g_c2[TSTEPS];
__device__ float g_sigma[TSTEPS];

// ---------------------------------------------------------------------------
// mish(x) = x * tanh(softplus(x)), softplus in the numerically-stable jax form
// ---------------------------------------------------------------------------
__device__ __forceinline__ float mishf(float x) {
    float sp = fmaxf(x, 0.0f) + log1pf(expf(-fabsf(x)));
    return x * tanhf(sp);
}

// ---------------------------------------------------------------------------
// Prolog: block 0/thread 0 computes the VP schedule in double (matches numpy
// f64 -> f32 cast). Every block b computes temb[b] (time MLP on the scalar
// timestep — batch-invariant, so it is hoisted out of the 2048-row loop).
// ---------------------------------------------------------------------------
__global__ void __launch_bounds__(256) prolog_kernel(
    const float* __restrict__ tW1, const float* __restrict__ tb1,
    const float* __restrict__ tW2, const float* __restrict__ tb2)
{
    const int tid = threadIdx.x;
    const int i   = blockIdx.x;

    if (i == 0 && tid == 0) {
        const double T = (double)TSTEPS, bmax = 10.0, bmin = 0.1;
        double ac = 1.0;
        for (int idx = 0; idx < TSTEPS; ++idx) {
            double t      = (double)(idx + 1);
            double alpha  = exp(-bmin / T - 0.5 * (bmax - bmin) * (2.0 * t - 1.0) / (T * T));
            double beta   = 1.0 - alpha;
            double acp    = ac;          // ac_prev
            ac            = ac * alpha;
            g_srac[idx]   = (float)sqrt(1.0 / ac);
            g_sracm1[idx] = (float)sqrt(1.0 / ac - 1.0);
            g_c1[idx]     = (float)(beta * sqrt(acp) / (1.0 - ac));
            g_c2[idx]     = (float)((1.0 - acp) * sqrt(alpha) / (1.0 - ac));
            double pv     = beta * (1.0 - acp) / (1.0 - ac);
            if (pv < 1e-20) pv = 1e-20;
            g_sigma[idx]  = (float)exp(0.5 * log(pv));   // NOISE_RATIO = 1
        }
    }

    // time MLP for timestep value t_float = i
    __shared__ float emb[TDIM];
    __shared__ float hid[HID];

    if (tid < TDIM) {
        int   j    = tid & 15;
        float freq = expf((float)j * (-logf(10000.0f) / 15.0f));
        float ang  = (float)i * freq;
        emb[tid]   = (tid < 16) ? sinf(ang) : cosf(ang);
    }
    __syncthreads();

    // hidden = mish(emb @ tW1 + tb1)  (256 units, one per thread)
    {
        float a = tb1[tid];
#pragma unroll
        for (int j = 0; j < TDIM; ++j)
            a = fmaf(emb[j], tW1[j * HID + tid], a);
        hid[tid] = mishf(a);
    }
    __syncthreads();

    // temb = hidden @ tW2 + tb2  (32 outputs)
    if (tid < TDIM) {
        float a = tb2[tid];
#pragma unroll 8
        for (int h = 0; h < HID; ++h)
            a = fmaf(hid[h], tW2[h * TDIM + tid], a);
        g_temb[i * TDIM + tid] = a;
    }
}

// ---------------------------------------------------------------------------
// Copy x_init into the evolving state buffer (fresh every launch)
// ---------------------------------------------------------------------------
__global__ void init_x_kernel(const float* __restrict__ x_init) {
    int idx = blockIdx.x * blockDim.x + threadIdx.x;
    if (idx < BATCH * ADIM) g_x[idx] = x_init[idx];
}

// ---------------------------------------------------------------------------
// One dense layer: out[16][256] = act(in[16][K] @ W[K][256] + b)
// Thread = one output column; 16 fp32 accumulators (one per row).
// LDS are warp-broadcast (all threads read the same in[r][k..k+3]) -> no
// conflicts; weight LDGs are coalesced and L2-resident (all CTAs share them).
// ---------------------------------------------------------------------------
template <int K, bool MISH>
__device__ __forceinline__ void dense_layer(
    const float* __restrict__ in,   // smem [ROWS][K], 16B-aligned rows
    const float* __restrict__ W,    // gmem [K][256]
    const float* __restrict__ b,    // gmem [256]
    float* __restrict__ out)        // smem [ROWS][256]
{
    const int c = threadIdx.x;
    float acc[ROWS];
    const float bc = b[c];
#pragma unroll
    for (int r = 0; r < ROWS; ++r) acc[r] = bc;

#pragma unroll 4
    for (int k = 0; k < K; k += 4) {
        const float w0 = W[(k + 0) * HID + c];
        const float w1 = W[(k + 1) * HID + c];
        const float w2 = W[(k + 2) * HID + c];
        const float w3 = W[(k + 3) * HID + c];
#pragma unroll
        for (int r = 0; r < ROWS; ++r) {
            float4 h = *reinterpret_cast<const float4*>(in + r * K + k);
            acc[r] = fmaf(h.x, w0, acc[r]);
            acc[r] = fmaf(h.y, w1, acc[r]);
            acc[r] = fmaf(h.z, w2, acc[r]);
            acc[r] = fmaf(h.w, w3, acc[r]);
        }
    }

#pragma unroll
    for (int r = 0; r < ROWS; ++r)
        out[r * HID + c] = MISH ? mishf(acc[r]) : acc[r];
    __syncthreads();
}

// ---------------------------------------------------------------------------
// One diffusion step for 16 rows: build h0 = [x, temb, state], run 4 layers,
// apply predict_start_from_noise + q_posterior + noise injection in-place.
// ---------------------------------------------------------------------------
__global__ void __launch_bounds__(256) step_kernel(
    const float* __restrict__ state,
    const float* __restrict__ noise_s,   // this step's noise slice [BATCH][ADIM]
    const float* __restrict__ W1, const float* __restrict__ b1,
    const float* __restrict__ W2, const float* __restrict__ b2,
    const float* __restrict__ W3, const float* __restrict__ b3,
    const float* __restrict__ W4, const float* __restrict__ b4,
    int i, float* __restrict__ out_final)
{
    __shared__ __align__(16) float h0[ROWS * CAT];   //  7.0 KB
    __shared__ __align__(16) float hA[ROWS * HID];   // 16.0 KB
    __shared__ __align__(16) float hB[ROWS * HID];   // 16.0 KB

    const int tid  = threadIdx.x;
    const int row0 = blockIdx.x * ROWS;

    // ---- assemble h0 = concat([x, temb, state]) for our 16 rows ----
    {   // x: 16x16
        int r = tid >> 4, c = tid & 15;
        h0[r * CAT + c] = g_x[(row0 + r) * ADIM + c];
    }
#pragma unroll
    for (int p = 0; p < 2; ++p) {  // temb: 16x32 (row-invariant broadcast)
        int idx = tid + p * 256;
        int r = idx >> 5, j = idx & 31;
        h0[r * CAT + ADIM + j] = g_temb[i * TDIM + j];
    }
#pragma unroll
    for (int p = 0; p < 4; ++p) {  // state: 16x64
        int idx = tid + p * 256;
        int r = idx >> 6, j = idx & 63;
        h0[r * CAT + ADIM + TDIM + j] = state[(row0 + r) * SDIM + j];
    }
    __syncthreads();

    dense_layer<CAT, true>(h0, W1, b1, hA);
    dense_layer<HID, true>(hA, W2, b2, hB);
    dense_layer<HID, true>(hB, W3, b3, hA);

    // ---- layer 4 (256 -> 16) + posterior update: thread = (row, col) ----
    {
        const int r = tid >> 4, c = tid & 15;
        float acc = b4[c];
#pragma unroll 4
        for (int k = 0; k < HID; k += 4) {
            float4 h = *reinterpret_cast<const float4*>(hA + r * HID + k);
            acc = fmaf(h.x, W4[(k + 0) * ADIM + c], acc);
            acc = fmaf(h.y, W4[(k + 1) * ADIM + c], acc);
            acc = fmaf(h.z, W4[(k + 2) * ADIM + c], acc);
            acc = fmaf(h.w, W4[(k + 3) * ADIM + c], acc);
        }

        const float x_old = h0[r * CAT + c];
        float xr = g_srac[i] * x_old - g_sracm1[i] * acc;
        xr = fminf(fmaxf(xr, -1.0f), 1.0f);                 // clip_denoised
        const float mean = g_c1[i] * xr + g_c2[i] * x_old;

        const int gidx = (row0 + r) * ADIM + c;
        if (i > 0) {
            g_x[gidx] = fmaf(g_sigma[i], noise_s[gidx], mean);
        } else {
            out_final[gidx] = fminf(fmaxf(mean, -1.0f), 1.0f);  // final clip
        }
    }
}

// ---------------------------------------------------------------------------
// kernel_launch: prolog + init + 100 sequential step kernels (graph-capturable,
// allocation-free, deterministic).
// ---------------------------------------------------------------------------
extern "C" void kernel_launch(void* const* d_in, const int* in_sizes, int n_in,
                              void* d_out, int out_size)
{
    const float* state  = (const float*)d_in[0];
    const float* x_init = (const float*)d_in[1];
    const float* noise  = (const float*)d_in[2];
    const float* tW1    = (const float*)d_in[3];
    const float* tb1    = (const float*)d_in[4];
    const float* tW2    = (const float*)d_in[5];
    const float* tb2    = (const float*)d_in[6];
    const float* W1     = (const float*)d_in[7];
    const float* b1     = (const float*)d_in[8];
    const float* W2     = (const float*)d_in[9];
    const float* b2     = (const float*)d_in[10];
    const float* W3     = (const float*)d_in[11];
    const float* b3     = (const float*)d_in[12];
    const float* W4     = (const float*)d_in[13];
    const float* b4     = (const float*)d_in[14];
    float* out          = (float*)d_out;

    prolog_kernel<<<TSTEPS, 256>>>(tW1, tb1, tW2, tb2);
    init_x_kernel<<<(BATCH * ADIM + 255) / 256, 256>>>(x_init);

    for (int s = 0; s < TSTEPS; ++s) {
        const int i = TSTEPS - 1 - s;                       // ts = 99..0
        const float* noise_s = noise + (size_t)s * BATCH * ADIM;
        step_kernel<<<NCTA, 256>>>(state, noise_s,
                                   W1, b1, W2, b2, W3, b3, W4, b4,
                                   i, out);
    }
}

// round 3
// speedup vs baseline: 1.0454x; 1.0454x over previous
#include <cuda_runtime.h>
#include <cuda_bf16.h>
#include <math.h>

// ---------------------------------------------------------------------------
// Problem constants
// ---------------------------------------------------------------------------
#define BATCH     2048
#define SDIM      64
#define ADIM      16
#define HID       256
#define TDIM      32
#define TSTEPS    100
#define CAT       112            // ADIM + TDIM + SDIM
#define RPC       8              // rows per CTA
#define PAIRS     4              // RPC/2 row-pairs (f32x2 packing)
#define NCTA      (BATCH / RPC)  // 256

// ---------------------------------------------------------------------------
// Precomputed schedule + time embeddings (written by prolog kernel)
// ---------------------------------------------------------------------------
__device__ float g_temb[TSTEPS * TDIM];
__device__ float g_srac[TSTEPS];
__device__ float g_sracm1[TSTEPS];
__device__ float g_c1[TSTEPS];
__device__ float g_c2[TSTEPS];
__device__ float g_sigma[TSTEPS];

// ---------------------------------------------------------------------------
// f32x2 helpers (packed dual-FMA, sm_100+)
// ---------------------------------------------------------------------------
__device__ __forceinline__ unsigned long long pack2(float lo, float hi) {
    unsigned long long r;
    asm("mov.b64 %0, {%1, %2};" : "=l"(r) : "f"(lo), "f"(hi));
    return r;
}
__device__ __forceinline__ void unpack2(unsigned long long v, float& lo, float& hi) {
    asm("mov.b64 {%0, %1}, %2;" : "=f"(lo), "=f"(hi) : "l"(v));
}
__device__ __forceinline__ void fma2(unsigned long long& d,
                                     unsigned long long a,
                                     unsigned long long b) {
    asm("fma.rn.f32x2 %0, %1, %2, %0;" : "+l"(d) : "l"(a), "l"(b));
}

// ---------------------------------------------------------------------------
// mish(x) = x * tanh(softplus(x))  (stable softplus, same as jax)
// ---------------------------------------------------------------------------
__device__ __forceinline__ float mishf(float x) {
    float sp = fmaxf(x, 0.0f) + log1pf(expf(-fabsf(x)));
    return x * tanhf(sp);
}

// ---------------------------------------------------------------------------
// Prolog: VP schedule in f64 (block0/thread0) + per-timestep time-MLP
// (batch-invariant, hoisted out of the 2048-row loop). One block per step.
// ---------------------------------------------------------------------------
__global__ void __launch_bounds__(256) prolog_kernel(
    const float* __restrict__ tW1, const float* __restrict__ tb1,
    const float* __restrict__ tW2, const float* __restrict__ tb2)
{
    const int tid = threadIdx.x;
    const int i   = blockIdx.x;

    if (i == 0 && tid == 0) {
        const double T = (double)TSTEPS, bmax = 10.0, bmin = 0.1;
        double ac = 1.0;
        for (int idx = 0; idx < TSTEPS; ++idx) {
            double t      = (double)(idx + 1);
            double alpha  = exp(-bmin / T - 0.5 * (bmax - bmin) * (2.0 * t - 1.0) / (T * T));
            double beta   = 1.0 - alpha;
            double acp    = ac;
            ac            = ac * alpha;
            g_srac[idx]   = (float)sqrt(1.0 / ac);
            g_sracm1[idx] = (float)sqrt(1.0 / ac - 1.0);
            g_c1[idx]     = (float)(beta * sqrt(acp) / (1.0 - ac));
            g_c2[idx]     = (float)((1.0 - acp) * sqrt(alpha) / (1.0 - ac));
            double pv     = beta * (1.0 - acp) / (1.0 - ac);
            if (pv < 1e-20) pv = 1e-20;
            g_sigma[idx]  = (float)exp(0.5 * log(pv));   // NOISE_RATIO = 1
        }
    }

    __shared__ float emb[TDIM];
    __shared__ float hid[HID];

    if (tid < TDIM) {
        int   j    = tid & 15;
        float freq = expf((float)j * (-logf(10000.0f) / 15.0f));
        float ang  = (float)i * freq;
        emb[tid]   = (tid < 16) ? sinf(ang) : cosf(ang);
    }
    __syncthreads();

    {   // hidden = mish(emb @ tW1 + tb1)
        float a = tb1[tid];
#pragma unroll
        for (int j = 0; j < TDIM; ++j)
            a = fmaf(emb[j], tW1[j * HID + tid], a);
        hid[tid] = mishf(a);
    }
    __syncthreads();

    if (tid < TDIM) {   // temb = hidden @ tW2 + tb2
        float a = tb2[tid];
#pragma unroll 8
        for (int h = 0; h < HID; ++h)
            a = fmaf(hid[h], tW2[h * TDIM + tid], a);
        g_temb[i * TDIM + tid] = a;
    }
}

// ---------------------------------------------------------------------------
// Dense layer with f32x2: out[c][j] = act( sum_k in[k][j] * W[k][c] + b[c] )
// in : smem, pair-packed  [K][PAIRS] float2   (all-thread broadcast reads)
// W  : gmem row-major [K][HID] (coalesced LDG.32 per k across threads)
// out: smem, pair-packed  [HID][PAIRS] float2 (becomes next layer's input)
// Thread = one output column c, 4 packed accumulators (8 rows).
// ---------------------------------------------------------------------------
template <int K, bool MISH>
__device__ __forceinline__ void dense2(
    const float2* __restrict__ in,
    const float*  __restrict__ W,
    const float*  __restrict__ b,
    float2* __restrict__ out)
{
    const int c = threadIdx.x;
    const float bc = b[c];
    unsigned long long acc0 = pack2(bc, bc);
    unsigned long long acc1 = acc0, acc2 = acc0, acc3 = acc0;

    const ulonglong2* __restrict__ inp = (const ulonglong2*)in;  // [K][2]

#pragma unroll 4
    for (int k = 0; k < K; ++k) {
        const float w = W[k * HID + c];
        const unsigned long long ww = pack2(w, w);
        const ulonglong2 p01 = inp[k * 2 + 0];   // pairs 0,1 (rows 0..3)
        const ulonglong2 p23 = inp[k * 2 + 1];   // pairs 2,3 (rows 4..7)
        fma2(acc0, p01.x, ww);
        fma2(acc1, p01.y, ww);
        fma2(acc2, p23.x, ww);
        fma2(acc3, p23.y, ww);
    }

    float lo, hi;
    unpack2(acc0, lo, hi);
    out[c * PAIRS + 0] = MISH ? make_float2(mishf(lo), mishf(hi)) : make_float2(lo, hi);
    unpack2(acc1, lo, hi);
    out[c * PAIRS + 1] = MISH ? make_float2(mishf(lo), mishf(hi)) : make_float2(lo, hi);
    unpack2(acc2, lo, hi);
    out[c * PAIRS + 2] = MISH ? make_float2(mishf(lo), mishf(hi)) : make_float2(lo, hi);
    unpack2(acc3, lo, hi);
    out[c * PAIRS + 3] = MISH ? make_float2(mishf(lo), mishf(hi)) : make_float2(lo, hi);
    __syncthreads();
}

// ---------------------------------------------------------------------------
// Fused sampler: one CTA owns 8 rows for all 100 steps. x lives inside the
// layer-1 input buffer (features 0..15) — the posterior update writes it back
// in place. No global state, no inter-step launches.
// ---------------------------------------------------------------------------
__global__ void __launch_bounds__(256, 2) sampler_kernel(
    const float* __restrict__ state,
    const float* __restrict__ x_init,
    const float* __restrict__ noise,     // [TSTEPS][BATCH][ADIM]
    const float* __restrict__ W1, const float* __restrict__ b1,
    const float* __restrict__ W2, const float* __restrict__ b2,
    const float* __restrict__ W3, const float* __restrict__ b3,
    const float* __restrict__ W4, const float* __restrict__ b4,
    float* __restrict__ out)
{
    __shared__ __align__(16) float2 a0[CAT * PAIRS];   // [112][4]  3.6 KB
    __shared__ __align__(16) float2 hA[HID * PAIRS];   // [256][4]  8.0 KB
    __shared__ __align__(16) float2 hB[HID * PAIRS];   // [256][4]  8.0 KB
    __shared__ __align__(16) float2 red[256];          // layer4 partials 2 KB

    const int tid  = threadIdx.x;
    const int row0 = blockIdx.x * RPC;

    // ---- one-time fills: x (features 0..15) and state (features 48..111) ----
    if (tid < 64) {                       // x: 16 cols x 4 pairs
        int c = tid >> 2, j = tid & 3;
        a0[c * PAIRS + j] = make_float2(x_init[(row0 + 2 * j)     * ADIM + c],
                                        x_init[(row0 + 2 * j + 1) * ADIM + c]);
    }
    {                                      // state: 64 feats x 4 pairs = 256
        int f = tid >> 2, j = tid & 3;
        a0[(ADIM + TDIM + f) * PAIRS + j] =
            make_float2(state[(row0 + 2 * j)     * SDIM + f],
                        state[(row0 + 2 * j + 1) * SDIM + f]);
    }

    // ---- 100 diffusion steps, fully CTA-local ----
    for (int s = 0; s < TSTEPS; ++s) {
        const int i = TSTEPS - 1 - s;

        // temb for this step: features 16..47 (row-invariant broadcast)
        if (tid < 128) {
            int m = tid >> 2, j = tid & 3;
            float t = g_temb[i * TDIM + m];
            a0[(ADIM + m) * PAIRS + j] = make_float2(t, t);
        }
        __syncthreads();

        dense2<CAT, true>(a0, W1, b1, hA);
        dense2<HID, true>(hA, W2, b2, hB);
        dense2<HID, true>(hB, W3, b3, hA);

        // ---- layer 4 (256 -> 16), k split 4 ways across the CTA ----
        {
            const int kc = tid >> 6;           // k-chunk 0..3
            const int r  = tid & 63;
            const int j  = r >> 4, c = r & 15; // pair, out col
            unsigned long long acc = pack2(0.0f, 0.0f);
            const int k0 = kc * 64;
#pragma unroll 4
            for (int k = k0; k < k0 + 64; ++k) {
                const float w = W4[k * ADIM + c];
                const unsigned long long ww = pack2(w, w);
                const unsigned long long hh =
                    *reinterpret_cast<const unsigned long long*>(&hA[k * PAIRS + j]);
                fma2(acc, hh, ww);
            }
            float lo, hi; unpack2(acc, lo, hi);
            red[tid] = make_float2(lo, hi);
        }
        __syncthreads();

        // ---- reduce + posterior update (64 threads: pair j, col c) ----
        if (tid < 64) {
            const int j = tid >> 4, c = tid & 15;
            float2 p0 = red[tid], p1 = red[tid + 64],
                   p2 = red[tid + 128], p3 = red[tid + 192];
            const float bb = b4[c];
            float ex = bb + p0.x + p1.x + p2.x + p3.x;  // eps_pred row 2j
            float ey = bb + p0.y + p1.y + p2.y + p3.y;  // eps_pred row 2j+1

            float2 x_old = a0[c * PAIRS + j];
            const float sr  = g_srac[i],  srm = g_sracm1[i];
            const float c1  = g_c1[i],    c2  = g_c2[i];

            float rx = fminf(fmaxf(sr * x_old.x - srm * ex, -1.0f), 1.0f);
            float ry = fminf(fmaxf(sr * x_old.y - srm * ey, -1.0f), 1.0f);
            float mx = c1 * rx + c2 * x_old.x;
            float my = c1 * ry + c2 * x_old.y;

            if (i > 0) {
                const float sg = g_sigma[i];
                const float* nz = noise + (size_t)s * BATCH * ADIM;
                float n0 = nz[(row0 + 2 * j)     * ADIM + c];
                float n1 = nz[(row0 + 2 * j + 1) * ADIM + c];
                a0[c * PAIRS + j] = make_float2(fmaf(sg, n0, mx),
                                                fmaf(sg, n1, my));
            } else {
                out[(row0 + 2 * j)     * ADIM + c] = fminf(fmaxf(mx, -1.0f), 1.0f);
                out[(row0 + 2 * j + 1) * ADIM + c] = fminf(fmaxf(my, -1.0f), 1.0f);
            }
        }
        __syncthreads();
    }
}

// ---------------------------------------------------------------------------
// kernel_launch: prolog + ONE fused sampler kernel (graph-capturable,
// allocation-free, deterministic).
// ---------------------------------------------------------------------------
extern "C" void kernel_launch(void* const* d_in, const int* in_sizes, int n_in,
                              void* d_out, int out_size)
{
    const float* state  = (const float*)d_in[0];
    const float* x_init = (const float*)d_in[1];
    const float* noise  = (const float*)d_in[2];
    const float* tW1    = (const float*)d_in[3];
    const float* tb1    = (const float*)d_in[4];
    const float* tW2    = (const float*)d_in[5];
    const float* tb2    = (const float*)d_in[6];
    const float* W1     = (const float*)d_in[7];
    const float* b1     = (const float*)d_in[8];
    const float* W2     = (const float*)d_in[9];
    const float* b2     = (const float*)d_in[10];
    const float* W3     = (const float*)d_in[11];
    const float* b3     = (const float*)d_in[12];
    const float* W4     = (const float*)d_in[13];
    const float* b4     = (const float*)d_in[14];
    float* out          = (float*)d_out;

    prolog_kernel<<<TSTEPS, 256>>>(tW1, tb1, tW2, tb2);
    sampler_kernel<<<NCTA, 256>>>(state, x_init, noise,
                                  W1, b1, W2, b2, W3, b3, W4, b4, out);
}